// round 4
// baseline (speedup 1.0000x reference)
#include <cuda_runtime.h>

// PatchesCreate: [64, 384, 384, 3] f32 -> [64, 576, 768] f32
//
// Tile decomposition: for fixed (b, gy) the 16 full image rows are a
// CONTIGUOUS 73728B input block, and they map exactly onto 24 consecutive
// patches = a CONTIGUOUS 73728B output block. So both GMEM streams are
// perfectly sequential; the permutation happens in SMEM.
//
// 1536 tiles (64 b x 24 gy), one CTA each: 512 threads x 9 float4.
//   load  (sequential, streaming) -> STS permuted -> sync -> store sequential.

static constexpr int TPB   = 512;
static constexpr int TILE4 = 16 * 288;        // 4608 float4 per tile (72KB)
static constexpr int LOADS = TILE4 / TPB;     // 9
static constexpr int SMEM_BYTES = TILE4 * 16; // 73728

__global__ void __launch_bounds__(TPB, 2)
patches_kernel(const float4* __restrict__ in, float4* __restrict__ out)
{
    extern __shared__ float4 sm[];

    int b  = blockIdx.x / 24;
    int gy = blockIdx.x - b * 24;

    const float4* __restrict__ src = in  + (b * 384 + gy * 16) * 288;
    float4*       __restrict__ dst = out + (b * 576 + gy * 24) * 192;

    // Phase 1: sequential streaming reads (batched for MLP)
    float4 v[LOADS];
#pragma unroll
    for (int j = 0; j < LOADS; ++j)
        v[j] = __ldcs(&src[threadIdx.x + j * TPB]);

    // Phase 2: permuted SMEM stores.
    // input-local idx -> (py = idx/288, r = idx%288, gx = r/12, lane = r%12)
    // output-local   = gx*192 + py*12 + lane
#pragma unroll
    for (int j = 0; j < LOADS; ++j) {
        int idx  = threadIdx.x + j * TPB;
        int py   = idx / 288;
        int r    = idx - py * 288;
        int gx   = r / 12;
        int lane = r - gx * 12;
        sm[gx * 192 + py * 12 + lane] = v[j];
    }
    __syncthreads();

    // Phase 3: sequential streaming writes
#pragma unroll
    for (int j = 0; j < LOADS; ++j) {
        int idx = threadIdx.x + j * TPB;
        __stcs(&dst[idx], sm[idx]);
    }
}

extern "C" void kernel_launch(void* const* d_in, const int* in_sizes, int n_in,
                              void* d_out, int out_size)
{
    (void)in_sizes; (void)n_in; (void)out_size;
    const float4* in  = (const float4*)d_in[0];
    float4*       out = (float4*)d_out;

    cudaFuncSetAttribute(patches_kernel,
                         cudaFuncAttributeMaxDynamicSharedMemorySize,
                         SMEM_BYTES);
    patches_kernel<<<64 * 24, TPB, SMEM_BYTES>>>(in, out);
}